// round 8
// baseline (speedup 1.0000x reference)
#include <cuda_runtime.h>
#include <cstdint>
#include <math.h>

// Problem constants: B=2, S=2048, D=1024, H=16, hd=64
#define SEQ   2048
#define DMODEL 1024
#define NH    16
#define HD    64
#define MTOT  4096   // B*S

// ---------------- scratch (no cudaMalloc allowed) ----------------
// All three hold tf32-rounded bits (converted in qkv_gemm epilogue).
// g_Q and g_K additionally store each 8-dim group pair-permuted:
//   within group: pos = ((d&3)<<1) | ((d&7)>>2)  so (d, d+4) are adjacent
//   -> A/B fragment column pairs (t, t+4) become contiguous 8-byte loads.
__device__ float g_Q[MTOT * DMODEL];
__device__ float g_K[MTOT * DMODEL];
__device__ float g_V[MTOT * DMODEL];

// ---------------- helpers ----------------
__device__ __forceinline__ uint32_t f2tf(float x) {
    uint32_t u;
    asm("cvt.rna.tf32.f32 %0, %1;" : "=r"(u) : "f"(x));
    return u;
}

__device__ __forceinline__ void mma8(float* c, const uint32_t* a, uint32_t b0, uint32_t b1) {
    asm volatile(
        "mma.sync.aligned.m16n8k8.row.col.f32.tf32.tf32.f32 "
        "{%0,%1,%2,%3}, {%4,%5,%6,%7}, {%8,%9}, {%0,%1,%2,%3};"
        : "+f"(c[0]), "+f"(c[1]), "+f"(c[2]), "+f"(c[3])
        : "r"(a[0]), "r"(a[1]), "r"(a[2]), "r"(a[3]), "r"(b0), "r"(b1));
}

// ======================================================================
// Kernel 1: QKV projection GEMM (structure unchanged — verified).
// Epilogue writes tf32-rounded values; Q AND K pair-permuted per 8-group.
// ======================================================================
__global__ __launch_bounds__(256) void qkv_gemm(
    const float* __restrict__ x,
    const float* __restrict__ Wq, const float* __restrict__ Wk, const float* __restrict__ Wv,
    const float* __restrict__ bq, const float* __restrict__ bk, const float* __restrict__ bv)
{
    __shared__ float As[128][36];   // frag bank (4g+t)%32, conflict-free
    __shared__ float Bs[32][136];   // frag bank (8t+g)%32, conflict-free

    const float* W; const float* bias; float* outp;
    if (blockIdx.z == 0)      { W = Wq; bias = bq; outp = g_Q; }
    else if (blockIdx.z == 1) { W = Wk; bias = bk; outp = g_K; }
    else                      { W = Wv; bias = bv; outp = g_V; }

    const int tid  = threadIdx.x;
    const int warp = tid >> 5, lane = tid & 31;
    const int g = lane >> 2, t = lane & 3;
    const int wr = warp >> 1;          // 0..3 (m)
    const int wc = warp & 1;           // 0..1 (n)
    const int m0 = blockIdx.y * 128;
    const int n0 = blockIdx.x * 128;

    float acc[2][8][4] = {};

    for (int k0 = 0; k0 < DMODEL; k0 += 32) {
        #pragma unroll
        for (int r = 0; r < 4; r++) {
            int i = tid + 256 * r;           // 0..1023
            int row = i >> 3;
            int c4  = (i & 7) << 2;
            float4 v = *(const float4*)&x[(m0 + row) * DMODEL + k0 + c4];
            As[row][c4 + 0] = __uint_as_float(f2tf(v.x));
            As[row][c4 + 1] = __uint_as_float(f2tf(v.y));
            As[row][c4 + 2] = __uint_as_float(f2tf(v.z));
            As[row][c4 + 3] = __uint_as_float(f2tf(v.w));
        }
        #pragma unroll
        for (int r = 0; r < 4; r++) {
            int i = tid + 256 * r;
            int row = i >> 5;
            int c4  = (i & 31) << 2;
            float4 v = *(const float4*)&W[(k0 + row) * DMODEL + n0 + c4];
            Bs[row][c4 + 0] = __uint_as_float(f2tf(v.x));
            Bs[row][c4 + 1] = __uint_as_float(f2tf(v.y));
            Bs[row][c4 + 2] = __uint_as_float(f2tf(v.z));
            Bs[row][c4 + 3] = __uint_as_float(f2tf(v.w));
        }
        __syncthreads();

        #pragma unroll
        for (int ks = 0; ks < 4; ks++) {
            const int kk = ks * 8;
            uint32_t a[2][4], bb[8][2];
            #pragma unroll
            for (int mt = 0; mt < 2; mt++) {
                int rb = wr * 32 + mt * 16;
                a[mt][0] = __float_as_uint(As[rb + g    ][kk + t    ]);
                a[mt][1] = __float_as_uint(As[rb + g + 8][kk + t    ]);
                a[mt][2] = __float_as_uint(As[rb + g    ][kk + t + 4]);
                a[mt][3] = __float_as_uint(As[rb + g + 8][kk + t + 4]);
            }
            #pragma unroll
            for (int nt = 0; nt < 8; nt++) {
                int cb = wc * 64 + nt * 8;
                bb[nt][0] = __float_as_uint(Bs[kk + t    ][cb + g]);
                bb[nt][1] = __float_as_uint(Bs[kk + t + 4][cb + g]);
            }
            #pragma unroll
            for (int mt = 0; mt < 2; mt++)
                #pragma unroll
                for (int nt = 0; nt < 8; nt++)
                    mma8(acc[mt][nt], a[mt], bb[nt][0], bb[nt][1]);
        }
        __syncthreads();
    }

    // epilogue: + bias, convert to tf32 bits, write.
    // Q and K get the pair-permute (both are read as column-paired frags).
    const bool doPerm = (blockIdx.z <= 1);
    #pragma unroll
    for (int mt = 0; mt < 2; mt++) {
        int row = m0 + wr * 32 + mt * 16 + g;
        #pragma unroll
        for (int nt = 0; nt < 8; nt++) {
            int col = n0 + wc * 64 + nt * 8 + 2 * t;
            float b0v = bias[col], b1v = bias[col + 1];
            float e00 = __uint_as_float(f2tf(acc[mt][nt][0] + b0v));
            float e01 = __uint_as_float(f2tf(acc[mt][nt][1] + b1v));
            float e10 = __uint_as_float(f2tf(acc[mt][nt][2] + b0v));
            float e11 = __uint_as_float(f2tf(acc[mt][nt][3] + b1v));
            if (doPerm) {
                // pair-permute within the 8-group: w -> ((w&3)<<1) | (w>>2)
                int wbase = col & ~7;
                int p0 = wbase + (((2 * t)     & 3) << 1) + (t >> 1);
                int p1 = wbase + (((2 * t + 1) & 3) << 1) + (t >> 1);
                outp[(size_t)row       * DMODEL + p0] = e00;
                outp[(size_t)row       * DMODEL + p1] = e01;
                outp[(size_t)(row + 8) * DMODEL + p0] = e10;
                outp[(size_t)(row + 8) * DMODEL + p1] = e11;
            } else {
                *(float2*)&outp[(size_t)row       * DMODEL + col] = make_float2(e00, e01);
                *(float2*)&outp[(size_t)(row + 8) * DMODEL + col] = make_float2(e10, e11);
            }
        }
    }
}

// ======================================================================
// Kernel 2: flash attention v6 = R1's proven shape (4 warps, 16 q-rows
// per warp, 64-row blocks, grid 1024, single-buffer fill) with the
// verified orthogonal wins:
//  - data pre-converted to tf32 in GEMM epilogue (no cvt in this kernel)
//  - K (and Q) pair-permuted in global -> S b-frags are single LDS.64,
//    fill is a pure byte copy
//  - paired P buffer -> A-frag reload is LDS.64; raw fp32 P store
// ======================================================================
#define KVT     32
#define KS_STRIDE 72
#define PS_STRIDE 40

__global__ __launch_bounds__(128) void attn_kernel(float* __restrict__ out)
{
    __shared__ float Ks[KVT][KS_STRIDE];   // paired-d layout (as in g_K)
    __shared__ float Vs[KVT][KS_STRIDE];   // plain [key][d]
    __shared__ float Ps[64][PS_STRIDE];    // paired-col P, 16 rows per warp

    const int tid = threadIdx.x, warp = tid >> 5, lane = tid & 31;
    const int g = lane >> 2, t = lane & 3;
    const int bh = blockIdx.y;
    const int b  = bh >> 4;
    const int h  = bh & 15;
    const int q0 = blockIdx.x * 64;

    const float* Kbase = g_K + (size_t)(b * SEQ) * DMODEL + h * HD;
    const float* Vbase = g_V + (size_t)(b * SEQ) * DMODEL + h * HD;

    // fill roles: thread -> (key row, 16-float chunk)
    const int frow = tid >> 2;              // 0..31
    const int fc   = (tid & 3) * 16;        // 0,16,32,48

    // --- Q fragments via paired LDG.64 (g_Q is permuted + tf32) ---
    const int qrow = b * SEQ + q0 + warp * 16;
    uint32_t qa[8][4];
    {
        const size_t r0 = (size_t)(qrow + g    ) * DMODEL + h * HD;
        const size_t r8 = (size_t)(qrow + g + 8) * DMODEL + h * HD;
        #pragma unroll
        for (int kt = 0; kt < 8; kt++) {
            float2 u0 = *(const float2*)&g_Q[r0 + kt * 8 + 2 * t];
            float2 u1 = *(const float2*)&g_Q[r8 + kt * 8 + 2 * t];
            qa[kt][0] = __float_as_uint(u0.x);
            qa[kt][1] = __float_as_uint(u1.x);
            qa[kt][2] = __float_as_uint(u0.y);
            qa[kt][3] = __float_as_uint(u1.y);
        }
    }

    float m2[2]  = {-INFINITY, -INFINITY};
    float ls[2]  = {0.f, 0.f};
    float o[8][4] = {};

    const float SC = 0.125f * 1.44269504088896f;  // 1/sqrt(64) * log2(e)

    // paired-column P store positions
    const int pkA = (((2 * t)     & 3) << 1) + (t >> 1);   // col 2t
    const int pkB = (((2 * t + 1) & 3) << 1) + (t >> 1);   // col 2t+1
    const int rg = warp * 16 + g;

    for (int kv0 = 0; kv0 < SEQ; kv0 += KVT) {
        // --- fill K,V: pure byte copy (tf32 + permute already done) ---
        {
            const float* kp = Kbase + (size_t)(kv0 + frow) * DMODEL + fc;
            const float* vp = Vbase + (size_t)(kv0 + frow) * DMODEL + fc;
            float4 k0v = *(const float4*)kp;
            float4 k1v = *(const float4*)(kp + 4);
            float4 k2v = *(const float4*)(kp + 8);
            float4 k3v = *(const float4*)(kp + 12);
            *(float4*)&Ks[frow][fc     ] = k0v;
            *(float4*)&Ks[frow][fc + 4 ] = k1v;
            *(float4*)&Ks[frow][fc + 8 ] = k2v;
            *(float4*)&Ks[frow][fc + 12] = k3v;
            float4 v0v = *(const float4*)vp;
            float4 v1v = *(const float4*)(vp + 4);
            float4 v2v = *(const float4*)(vp + 8);
            float4 v3v = *(const float4*)(vp + 12);
            *(float4*)&Vs[frow][fc     ] = v0v;
            *(float4*)&Vs[frow][fc + 4 ] = v1v;
            *(float4*)&Vs[frow][fc + 8 ] = v2v;
            *(float4*)&Vs[frow][fc + 12] = v3v;
        }
        __syncthreads();

        // --- S = Q @ K^T : K b-frags as single LDS.64 ---
        float s[4][4] = {};
        #pragma unroll
        for (int nt = 0; nt < 4; nt++) {
            #pragma unroll
            for (int kt = 0; kt < 8; kt++) {
                float2 bb = *(const float2*)&Ks[nt * 8 + g][kt * 8 + 2 * t];
                mma8(s[nt], qa[kt], __float_as_uint(bb.x), __float_as_uint(bb.y));
            }
        }

        // --- log2-domain scale + tile row max ---
        float mx0 = -INFINITY, mx1 = -INFINITY;
        #pragma unroll
        for (int nt = 0; nt < 4; nt++) {
            s[nt][0] *= SC; s[nt][1] *= SC; s[nt][2] *= SC; s[nt][3] *= SC;
            mx0 = fmaxf(mx0, fmaxf(s[nt][0], s[nt][1]));
            mx1 = fmaxf(mx1, fmaxf(s[nt][2], s[nt][3]));
        }
        mx0 = fmaxf(mx0, __shfl_xor_sync(0xffffffffu, mx0, 1));
        mx0 = fmaxf(mx0, __shfl_xor_sync(0xffffffffu, mx0, 2));
        mx1 = fmaxf(mx1, __shfl_xor_sync(0xffffffffu, mx1, 1));
        mx1 = fmaxf(mx1, __shfl_xor_sync(0xffffffffu, mx1, 2));

        float mn0 = fmaxf(m2[0], mx0);
        float mn1 = fmaxf(m2[1], mx1);
        float c0 = exp2f(m2[0] - mn0);
        float c1 = exp2f(m2[1] - mn1);
        m2[0] = mn0; m2[1] = mn1;
        ls[0] *= c0; ls[1] *= c1;
        #pragma unroll
        for (int nt = 0; nt < 8; nt++) {
            o[nt][0] *= c0; o[nt][1] *= c0;
            o[nt][2] *= c1; o[nt][3] *= c1;
        }

        // --- P = exp2(s - m), paired-col store (raw fp32; mma truncates) ---
        #pragma unroll
        for (int nt = 0; nt < 4; nt++) {
            float p0 = exp2f(s[nt][0] - mn0);
            float p1 = exp2f(s[nt][1] - mn0);
            float p2 = exp2f(s[nt][2] - mn1);
            float p3 = exp2f(s[nt][3] - mn1);
            ls[0] += p0 + p1;
            ls[1] += p2 + p3;
            Ps[rg    ][nt * 8 + pkA] = p0;
            Ps[rg    ][nt * 8 + pkB] = p1;
            Ps[rg + 8][nt * 8 + pkA] = p2;
            Ps[rg + 8][nt * 8 + pkB] = p3;
        }
        __syncwarp();

        // --- reload P as A-frags via LDS.64 ---
        uint32_t pa[4][4];
        #pragma unroll
        for (int kt = 0; kt < 4; kt++) {
            float2 u0 = *(const float2*)&Ps[rg    ][kt * 8 + 2 * t];
            float2 u1 = *(const float2*)&Ps[rg + 8][kt * 8 + 2 * t];
            pa[kt][0] = __float_as_uint(u0.x);
            pa[kt][1] = __float_as_uint(u1.x);
            pa[kt][2] = __float_as_uint(u0.y);
            pa[kt][3] = __float_as_uint(u1.y);
        }

        // --- O += P @ V ---
        #pragma unroll
        for (int nt = 0; nt < 8; nt++) {
            #pragma unroll
            for (int kt = 0; kt < 4; kt++) {
                uint32_t b0 = __float_as_uint(Vs[kt * 8 + t    ][nt * 8 + g]);
                uint32_t b1 = __float_as_uint(Vs[kt * 8 + t + 4][nt * 8 + g]);
                mma8(o[nt], pa[kt], b0, b1);
            }
        }

        __syncthreads();   // tile fully consumed before refill
    }

    // --- normalize and write out[b, s, h*64 + d] ---
    ls[0] += __shfl_xor_sync(0xffffffffu, ls[0], 1);
    ls[0] += __shfl_xor_sync(0xffffffffu, ls[0], 2);
    ls[1] += __shfl_xor_sync(0xffffffffu, ls[1], 1);
    ls[1] += __shfl_xor_sync(0xffffffffu, ls[1], 2);
    float i0 = 1.f / ls[0];
    float i1 = 1.f / ls[1];

    const int orow = b * SEQ + q0 + warp * 16;
    #pragma unroll
    for (int nt = 0; nt < 8; nt++) {
        int col = h * HD + nt * 8 + 2 * t;
        float2 v0 = make_float2(o[nt][0] * i0, o[nt][1] * i0);
        float2 v1 = make_float2(o[nt][2] * i1, o[nt][3] * i1);
        *(float2*)&out[(size_t)(orow + g    ) * DMODEL + col] = v0;
        *(float2*)&out[(size_t)(orow + g + 8) * DMODEL + col] = v1;
    }
}

// ======================================================================
// launch
// ======================================================================
extern "C" void kernel_launch(void* const* d_in, const int* in_sizes, int n_in,
                              void* d_out, int out_size)
{
    const float* x  = (const float*)d_in[0];
    const float* Wq = (const float*)d_in[1];
    const float* bq = (const float*)d_in[2];
    const float* Wk = (const float*)d_in[3];
    const float* bk = (const float*)d_in[4];
    const float* Wv = (const float*)d_in[5];
    const float* bv = (const float*)d_in[6];
    float* out = (float*)d_out;

    dim3 gg(DMODEL / 128, MTOT / 128, 3);   // (8, 32, 3)
    qkv_gemm<<<gg, 256>>>(x, Wq, Wk, Wv, bq, bk, bv);

    dim3 ga(SEQ / 64, 2 * NH);              // (32, 32)
    attn_kernel<<<ga, 128>>>(out);
}

// round 9
// speedup vs baseline: 1.2047x; 1.2047x over previous
#include <cuda_runtime.h>
#include <cstdint>
#include <math.h>

// Problem constants: B=2, S=2048, D=1024, H=16, hd=64
#define SEQ   2048
#define DMODEL 1024
#define NH    16
#define HD    64
#define MTOT  4096   // B*S

// ---------------- scratch (no cudaMalloc allowed) ----------------
// All three hold tf32-rounded bits (converted in qkv_gemm epilogue).
// g_Q and g_K additionally store each 8-dim group pair-permuted:
//   within group: pos = ((d&3)<<1) | ((d&7)>>2)  so (d, d+4) are adjacent
//   -> A/B fragment column pairs (t, t+4) become contiguous 8-byte loads.
__device__ float g_Q[MTOT * DMODEL];
__device__ float g_K[MTOT * DMODEL];
__device__ float g_V[MTOT * DMODEL];

// ---------------- helpers ----------------
__device__ __forceinline__ uint32_t f2tf(float x) {
    uint32_t u;
    asm("cvt.rna.tf32.f32 %0, %1;" : "=r"(u) : "f"(x));
    return u;
}

__device__ __forceinline__ void mma8(float* c, const uint32_t* a, uint32_t b0, uint32_t b1) {
    asm volatile(
        "mma.sync.aligned.m16n8k8.row.col.f32.tf32.tf32.f32 "
        "{%0,%1,%2,%3}, {%4,%5,%6,%7}, {%8,%9}, {%0,%1,%2,%3};"
        : "+f"(c[0]), "+f"(c[1]), "+f"(c[2]), "+f"(c[3])
        : "r"(a[0]), "r"(a[1]), "r"(a[2]), "r"(a[3]), "r"(b0), "r"(b1));
}

// ======================================================================
// Kernel 1: QKV projection GEMM (unchanged — verified).
// Epilogue writes tf32-rounded values; Q AND K pair-permuted per 8-group.
// ======================================================================
__global__ __launch_bounds__(256) void qkv_gemm(
    const float* __restrict__ x,
    const float* __restrict__ Wq, const float* __restrict__ Wk, const float* __restrict__ Wv,
    const float* __restrict__ bq, const float* __restrict__ bk, const float* __restrict__ bv)
{
    __shared__ float As[128][36];   // frag bank (4g+t)%32, conflict-free
    __shared__ float Bs[32][136];   // frag bank (8t+g)%32, conflict-free

    const float* W; const float* bias; float* outp;
    if (blockIdx.z == 0)      { W = Wq; bias = bq; outp = g_Q; }
    else if (blockIdx.z == 1) { W = Wk; bias = bk; outp = g_K; }
    else                      { W = Wv; bias = bv; outp = g_V; }

    const int tid  = threadIdx.x;
    const int warp = tid >> 5, lane = tid & 31;
    const int g = lane >> 2, t = lane & 3;
    const int wr = warp >> 1;          // 0..3 (m)
    const int wc = warp & 1;           // 0..1 (n)
    const int m0 = blockIdx.y * 128;
    const int n0 = blockIdx.x * 128;

    float acc[2][8][4] = {};

    for (int k0 = 0; k0 < DMODEL; k0 += 32) {
        #pragma unroll
        for (int r = 0; r < 4; r++) {
            int i = tid + 256 * r;           // 0..1023
            int row = i >> 3;
            int c4  = (i & 7) << 2;
            float4 v = *(const float4*)&x[(m0 + row) * DMODEL + k0 + c4];
            As[row][c4 + 0] = __uint_as_float(f2tf(v.x));
            As[row][c4 + 1] = __uint_as_float(f2tf(v.y));
            As[row][c4 + 2] = __uint_as_float(f2tf(v.z));
            As[row][c4 + 3] = __uint_as_float(f2tf(v.w));
        }
        #pragma unroll
        for (int r = 0; r < 4; r++) {
            int i = tid + 256 * r;
            int row = i >> 5;
            int c4  = (i & 31) << 2;
            float4 v = *(const float4*)&W[(k0 + row) * DMODEL + n0 + c4];
            Bs[row][c4 + 0] = __uint_as_float(f2tf(v.x));
            Bs[row][c4 + 1] = __uint_as_float(f2tf(v.y));
            Bs[row][c4 + 2] = __uint_as_float(f2tf(v.z));
            Bs[row][c4 + 3] = __uint_as_float(f2tf(v.w));
        }
        __syncthreads();

        #pragma unroll
        for (int ks = 0; ks < 4; ks++) {
            const int kk = ks * 8;
            uint32_t a[2][4], bb[8][2];
            #pragma unroll
            for (int mt = 0; mt < 2; mt++) {
                int rb = wr * 32 + mt * 16;
                a[mt][0] = __float_as_uint(As[rb + g    ][kk + t    ]);
                a[mt][1] = __float_as_uint(As[rb + g + 8][kk + t    ]);
                a[mt][2] = __float_as_uint(As[rb + g    ][kk + t + 4]);
                a[mt][3] = __float_as_uint(As[rb + g + 8][kk + t + 4]);
            }
            #pragma unroll
            for (int nt = 0; nt < 8; nt++) {
                int cb = wc * 64 + nt * 8;
                bb[nt][0] = __float_as_uint(Bs[kk + t    ][cb + g]);
                bb[nt][1] = __float_as_uint(Bs[kk + t + 4][cb + g]);
            }
            #pragma unroll
            for (int mt = 0; mt < 2; mt++)
                #pragma unroll
                for (int nt = 0; nt < 8; nt++)
                    mma8(acc[mt][nt], a[mt], bb[nt][0], bb[nt][1]);
        }
        __syncthreads();
    }

    // epilogue: + bias, convert to tf32 bits, write.
    // Q and K get the pair-permute (both are read as column-paired frags).
    const bool doPerm = (blockIdx.z <= 1);
    #pragma unroll
    for (int mt = 0; mt < 2; mt++) {
        int row = m0 + wr * 32 + mt * 16 + g;
        #pragma unroll
        for (int nt = 0; nt < 8; nt++) {
            int col = n0 + wc * 64 + nt * 8 + 2 * t;
            float b0v = bias[col], b1v = bias[col + 1];
            float e00 = __uint_as_float(f2tf(acc[mt][nt][0] + b0v));
            float e01 = __uint_as_float(f2tf(acc[mt][nt][1] + b1v));
            float e10 = __uint_as_float(f2tf(acc[mt][nt][2] + b0v));
            float e11 = __uint_as_float(f2tf(acc[mt][nt][3] + b1v));
            if (doPerm) {
                // pair-permute within the 8-group: w -> ((w&3)<<1) | (w>>2)
                int wbase = col & ~7;
                int p0 = wbase + (((2 * t)     & 3) << 1) + (t >> 1);
                int p1 = wbase + (((2 * t + 1) & 3) << 1) + (t >> 1);
                outp[(size_t)row       * DMODEL + p0] = e00;
                outp[(size_t)row       * DMODEL + p1] = e01;
                outp[(size_t)(row + 8) * DMODEL + p0] = e10;
                outp[(size_t)(row + 8) * DMODEL + p1] = e11;
            } else {
                *(float2*)&outp[(size_t)row       * DMODEL + col] = make_float2(e00, e01);
                *(float2*)&outp[(size_t)(row + 8) * DMODEL + col] = make_float2(e10, e11);
            }
        }
    }
}

// ======================================================================
// Kernel 2: flash attention v6b — identical to v6 except
// __launch_bounds__(128, 4): forces <=128 regs so 4 blocks/SM fit and
// grid 1024 runs in 2 waves (148*4=592 slots), not 3. R8's regression
// was the 131-reg occupancy cliff (3 blocks/SM -> 3 waves).
// ======================================================================
#define KVT     32
#define KS_STRIDE 72
#define PS_STRIDE 40

__global__ __launch_bounds__(128, 4) void attn_kernel(float* __restrict__ out)
{
    __shared__ float Ks[KVT][KS_STRIDE];   // paired-d layout (as in g_K)
    __shared__ float Vs[KVT][KS_STRIDE];   // plain [key][d]
    __shared__ float Ps[64][PS_STRIDE];    // paired-col P, 16 rows per warp

    const int tid = threadIdx.x, warp = tid >> 5, lane = tid & 31;
    const int g = lane >> 2, t = lane & 3;
    const int bh = blockIdx.y;
    const int b  = bh >> 4;
    const int h  = bh & 15;
    const int q0 = blockIdx.x * 64;

    const float* Kbase = g_K + (size_t)(b * SEQ) * DMODEL + h * HD;
    const float* Vbase = g_V + (size_t)(b * SEQ) * DMODEL + h * HD;

    // fill roles: thread -> (key row, 16-float chunk)
    const int frow = tid >> 2;              // 0..31
    const int fc   = (tid & 3) * 16;        // 0,16,32,48

    // --- Q fragments via paired LDG.64 (g_Q is permuted + tf32) ---
    const int qrow = b * SEQ + q0 + warp * 16;
    uint32_t qa[8][4];
    {
        const size_t r0 = (size_t)(qrow + g    ) * DMODEL + h * HD;
        const size_t r8 = (size_t)(qrow + g + 8) * DMODEL + h * HD;
        #pragma unroll
        for (int kt = 0; kt < 8; kt++) {
            float2 u0 = *(const float2*)&g_Q[r0 + kt * 8 + 2 * t];
            float2 u1 = *(const float2*)&g_Q[r8 + kt * 8 + 2 * t];
            qa[kt][0] = __float_as_uint(u0.x);
            qa[kt][1] = __float_as_uint(u1.x);
            qa[kt][2] = __float_as_uint(u0.y);
            qa[kt][3] = __float_as_uint(u1.y);
        }
    }

    float m2[2]  = {-INFINITY, -INFINITY};
    float ls[2]  = {0.f, 0.f};
    float o[8][4] = {};

    const float SC = 0.125f * 1.44269504088896f;  // 1/sqrt(64) * log2(e)

    // paired-column P store positions
    const int pkA = (((2 * t)     & 3) << 1) + (t >> 1);   // col 2t
    const int pkB = (((2 * t + 1) & 3) << 1) + (t >> 1);   // col 2t+1
    const int rg = warp * 16 + g;

    for (int kv0 = 0; kv0 < SEQ; kv0 += KVT) {
        // --- fill K,V: pure byte copy (tf32 + permute already done) ---
        {
            const float* kp = Kbase + (size_t)(kv0 + frow) * DMODEL + fc;
            const float* vp = Vbase + (size_t)(kv0 + frow) * DMODEL + fc;
            float4 k0v = *(const float4*)kp;
            float4 k1v = *(const float4*)(kp + 4);
            float4 k2v = *(const float4*)(kp + 8);
            float4 k3v = *(const float4*)(kp + 12);
            *(float4*)&Ks[frow][fc     ] = k0v;
            *(float4*)&Ks[frow][fc + 4 ] = k1v;
            *(float4*)&Ks[frow][fc + 8 ] = k2v;
            *(float4*)&Ks[frow][fc + 12] = k3v;
            float4 v0v = *(const float4*)vp;
            float4 v1v = *(const float4*)(vp + 4);
            float4 v2v = *(const float4*)(vp + 8);
            float4 v3v = *(const float4*)(vp + 12);
            *(float4*)&Vs[frow][fc     ] = v0v;
            *(float4*)&Vs[frow][fc + 4 ] = v1v;
            *(float4*)&Vs[frow][fc + 8 ] = v2v;
            *(float4*)&Vs[frow][fc + 12] = v3v;
        }
        __syncthreads();

        // --- S = Q @ K^T : K b-frags as single LDS.64 ---
        float s[4][4] = {};
        #pragma unroll
        for (int nt = 0; nt < 4; nt++) {
            #pragma unroll
            for (int kt = 0; kt < 8; kt++) {
                float2 bb = *(const float2*)&Ks[nt * 8 + g][kt * 8 + 2 * t];
                mma8(s[nt], qa[kt], __float_as_uint(bb.x), __float_as_uint(bb.y));
            }
        }

        // --- log2-domain scale + tile row max ---
        float mx0 = -INFINITY, mx1 = -INFINITY;
        #pragma unroll
        for (int nt = 0; nt < 4; nt++) {
            s[nt][0] *= SC; s[nt][1] *= SC; s[nt][2] *= SC; s[nt][3] *= SC;
            mx0 = fmaxf(mx0, fmaxf(s[nt][0], s[nt][1]));
            mx1 = fmaxf(mx1, fmaxf(s[nt][2], s[nt][3]));
        }
        mx0 = fmaxf(mx0, __shfl_xor_sync(0xffffffffu, mx0, 1));
        mx0 = fmaxf(mx0, __shfl_xor_sync(0xffffffffu, mx0, 2));
        mx1 = fmaxf(mx1, __shfl_xor_sync(0xffffffffu, mx1, 1));
        mx1 = fmaxf(mx1, __shfl_xor_sync(0xffffffffu, mx1, 2));

        float mn0 = fmaxf(m2[0], mx0);
        float mn1 = fmaxf(m2[1], mx1);
        float c0 = exp2f(m2[0] - mn0);
        float c1 = exp2f(m2[1] - mn1);
        m2[0] = mn0; m2[1] = mn1;
        ls[0] *= c0; ls[1] *= c1;
        #pragma unroll
        for (int nt = 0; nt < 8; nt++) {
            o[nt][0] *= c0; o[nt][1] *= c0;
            o[nt][2] *= c1; o[nt][3] *= c1;
        }

        // --- P = exp2(s - m), paired-col store (raw fp32; mma truncates) ---
        #pragma unroll
        for (int nt = 0; nt < 4; nt++) {
            float p0 = exp2f(s[nt][0] - mn0);
            float p1 = exp2f(s[nt][1] - mn0);
            float p2 = exp2f(s[nt][2] - mn1);
            float p3 = exp2f(s[nt][3] - mn1);
            ls[0] += p0 + p1;
            ls[1] += p2 + p3;
            Ps[rg    ][nt * 8 + pkA] = p0;
            Ps[rg    ][nt * 8 + pkB] = p1;
            Ps[rg + 8][nt * 8 + pkA] = p2;
            Ps[rg + 8][nt * 8 + pkB] = p3;
        }
        __syncwarp();

        // --- reload P as A-frags via LDS.64 ---
        uint32_t pa[4][4];
        #pragma unroll
        for (int kt = 0; kt < 4; kt++) {
            float2 u0 = *(const float2*)&Ps[rg    ][kt * 8 + 2 * t];
            float2 u1 = *(const float2*)&Ps[rg + 8][kt * 8 + 2 * t];
            pa[kt][0] = __float_as_uint(u0.x);
            pa[kt][1] = __float_as_uint(u1.x);
            pa[kt][2] = __float_as_uint(u0.y);
            pa[kt][3] = __float_as_uint(u1.y);
        }

        // --- O += P @ V ---
        #pragma unroll
        for (int nt = 0; nt < 8; nt++) {
            #pragma unroll
            for (int kt = 0; kt < 4; kt++) {
                uint32_t b0 = __float_as_uint(Vs[kt * 8 + t    ][nt * 8 + g]);
                uint32_t b1 = __float_as_uint(Vs[kt * 8 + t + 4][nt * 8 + g]);
                mma8(o[nt], pa[kt], b0, b1);
            }
        }

        __syncthreads();   // tile fully consumed before refill
    }

    // --- normalize and write out[b, s, h*64 + d] ---
    ls[0] += __shfl_xor_sync(0xffffffffu, ls[0], 1);
    ls[0] += __shfl_xor_sync(0xffffffffu, ls[0], 2);
    ls[1] += __shfl_xor_sync(0xffffffffu, ls[1], 1);
    ls[1] += __shfl_xor_sync(0xffffffffu, ls[1], 2);
    float i0 = 1.f / ls[0];
    float i1 = 1.f / ls[1];

    const int orow = b * SEQ + q0 + warp * 16;
    #pragma unroll
    for (int nt = 0; nt < 8; nt++) {
        int col = h * HD + nt * 8 + 2 * t;
        float2 v0 = make_float2(o[nt][0] * i0, o[nt][1] * i0);
        float2 v1 = make_float2(o[nt][2] * i1, o[nt][3] * i1);
        *(float2*)&out[(size_t)(orow + g    ) * DMODEL + col] = v0;
        *(float2*)&out[(size_t)(orow + g + 8) * DMODEL + col] = v1;
    }
}

// ======================================================================
// launch
// ======================================================================
extern "C" void kernel_launch(void* const* d_in, const int* in_sizes, int n_in,
                              void* d_out, int out_size)
{
    const float* x  = (const float*)d_in[0];
    const float* Wq = (const float*)d_in[1];
    const float* bq = (const float*)d_in[2];
    const float* Wk = (const float*)d_in[3];
    const float* bk = (const float*)d_in[4];
    const float* Wv = (const float*)d_in[5];
    const float* bv = (const float*)d_in[6];
    float* out = (float*)d_out;

    dim3 gg(DMODEL / 128, MTOT / 128, 3);   // (8, 32, 3)
    qkv_gemm<<<gg, 256>>>(x, Wq, Wk, Wv, bq, bk, bv);

    dim3 ga(SEQ / 64, 2 * NH);              // (32, 32)
    attn_kernel<<<ga, 128>>>(out);
}

// round 11
// speedup vs baseline: 1.5050x; 1.2492x over previous
#include <cuda_runtime.h>
#include <cstdint>
#include <math.h>

// Problem constants: B=2, S=2048, D=1024, H=16, hd=64
#define SEQ   2048
#define DMODEL 1024
#define NH    16
#define HD    64
#define MTOT  4096   // B*S

// ---------------- scratch (no cudaMalloc allowed) ----------------
__device__ float g_Q[MTOT * DMODEL];
__device__ float g_K[MTOT * DMODEL];
__device__ float g_V[MTOT * DMODEL];

// ---------------- helpers ----------------
__device__ __forceinline__ uint32_t f2tf(float x) {
    uint32_t u;
    asm("cvt.rna.tf32.f32 %0, %1;" : "=r"(u) : "f"(x));
    return u;
}

__device__ __forceinline__ void mma8(float* c, const uint32_t* a, uint32_t b0, uint32_t b1) {
    asm volatile(
        "mma.sync.aligned.m16n8k8.row.col.f32.tf32.tf32.f32 "
        "{%0,%1,%2,%3}, {%4,%5,%6,%7}, {%8,%9}, {%0,%1,%2,%3};"
        : "+f"(c[0]), "+f"(c[1]), "+f"(c[2]), "+f"(c[3])
        : "r"(a[0]), "r"(a[1]), "r"(a[2]), "r"(a[3]), "r"(b0), "r"(b1));
}

// ======================================================================
// Kernel 1: QKV projection GEMM — R1 inner code, restructured:
//  - grid (8, 32): 256 blocks, one wave at 2 blocks/SM (no 59%-full
//    tail wave of the old 768-block grid)
//  - phase loop (Wq, Wk, Wv) inside the block, acc re-zeroed per phase
//  - __launch_bounds__(256, 2) pins <=128 regs (no occupancy cliff)
// Epilogue identical to R1: raw fp32 + bias, plain float2 stores.
// ======================================================================
__global__ __launch_bounds__(256, 2) void qkv_gemm(
    const float* __restrict__ x,
    const float* __restrict__ Wq, const float* __restrict__ Wk, const float* __restrict__ Wv,
    const float* __restrict__ bq, const float* __restrict__ bk, const float* __restrict__ bv)
{
    __shared__ float As[128][36];   // pad 36: frag bank = (4g+t)%32, conflict-free
    __shared__ float Bs[32][136];   // pad 136: frag bank = (8t+g)%32, conflict-free

    const int tid  = threadIdx.x;
    const int warp = tid >> 5, lane = tid & 31;
    const int g = lane >> 2, t = lane & 3;
    const int wr = warp >> 1;          // 0..3 (m)
    const int wc = warp & 1;           // 0..1 (n)
    const int m0 = blockIdx.y * 128;
    const int n0 = blockIdx.x * 128;

    #pragma unroll 1
    for (int phase = 0; phase < 3; phase++) {
        const float* W    = (phase == 0) ? Wq : (phase == 1) ? Wk : Wv;
        const float* bias = (phase == 0) ? bq : (phase == 1) ? bk : bv;
        float* outp       = (phase == 0) ? g_Q : (phase == 1) ? g_K : g_V;

        float acc[2][8][4] = {};

        for (int k0 = 0; k0 < DMODEL; k0 += 32) {
            // load A tile 128x32 (convert fp32 -> tf32 once)
            #pragma unroll
            for (int r = 0; r < 4; r++) {
                int i = tid + 256 * r;           // 0..1023
                int row = i >> 3;
                int c4  = (i & 7) << 2;
                float4 v = *(const float4*)&x[(m0 + row) * DMODEL + k0 + c4];
                As[row][c4 + 0] = __uint_as_float(f2tf(v.x));
                As[row][c4 + 1] = __uint_as_float(f2tf(v.y));
                As[row][c4 + 2] = __uint_as_float(f2tf(v.z));
                As[row][c4 + 3] = __uint_as_float(f2tf(v.w));
            }
            // load B tile 32x128
            #pragma unroll
            for (int r = 0; r < 4; r++) {
                int i = tid + 256 * r;
                int row = i >> 5;
                int c4  = (i & 31) << 2;
                float4 v = *(const float4*)&W[(k0 + row) * DMODEL + n0 + c4];
                Bs[row][c4 + 0] = __uint_as_float(f2tf(v.x));
                Bs[row][c4 + 1] = __uint_as_float(f2tf(v.y));
                Bs[row][c4 + 2] = __uint_as_float(f2tf(v.z));
                Bs[row][c4 + 3] = __uint_as_float(f2tf(v.w));
            }
            __syncthreads();

            #pragma unroll
            for (int ks = 0; ks < 4; ks++) {
                const int kk = ks * 8;
                uint32_t a[2][4], bb[8][2];
                #pragma unroll
                for (int mt = 0; mt < 2; mt++) {
                    int rb = wr * 32 + mt * 16;
                    a[mt][0] = __float_as_uint(As[rb + g    ][kk + t    ]);
                    a[mt][1] = __float_as_uint(As[rb + g + 8][kk + t    ]);
                    a[mt][2] = __float_as_uint(As[rb + g    ][kk + t + 4]);
                    a[mt][3] = __float_as_uint(As[rb + g + 8][kk + t + 4]);
                }
                #pragma unroll
                for (int nt = 0; nt < 8; nt++) {
                    int cb = wc * 64 + nt * 8;
                    bb[nt][0] = __float_as_uint(Bs[kk + t    ][cb + g]);
                    bb[nt][1] = __float_as_uint(Bs[kk + t + 4][cb + g]);
                }
                #pragma unroll
                for (int mt = 0; mt < 2; mt++)
                    #pragma unroll
                    for (int nt = 0; nt < 8; nt++)
                        mma8(acc[mt][nt], a[mt], bb[nt][0], bb[nt][1]);
            }
            __syncthreads();
        }

        // epilogue: + bias, write row-major (raw fp32, as in R1)
        #pragma unroll
        for (int mt = 0; mt < 2; mt++) {
            int row = m0 + wr * 32 + mt * 16 + g;
            #pragma unroll
            for (int nt = 0; nt < 8; nt++) {
                int col = n0 + wc * 64 + nt * 8 + 2 * t;
                float b0v = bias[col], b1v = bias[col + 1];
                float2 v0 = make_float2(acc[mt][nt][0] + b0v, acc[mt][nt][1] + b1v);
                float2 v1 = make_float2(acc[mt][nt][2] + b0v, acc[mt][nt][3] + b1v);
                *(float2*)&outp[(size_t)row       * DMODEL + col] = v0;
                *(float2*)&outp[(size_t)(row + 8) * DMODEL + col] = v1;
            }
        }
    }
}

// ======================================================================
// Kernel 2: flash attention — EXACT R1 content (the verified 293us
// kernel). grid = (SEQ/64, B*NH), 128 threads (4 warps), each warp owns
// 16 q-rows x all keys. KV tiles of 32 keys.
// ======================================================================
__global__ __launch_bounds__(128) void attn_kernel(float* __restrict__ out)
{
    __shared__ float Ks[32][68];   // frag bank (4g+t)%32 conflict-free
    __shared__ float Vs[32][72];   // frag bank (8t+g)%32 conflict-free
    __shared__ float Ps[64][36];   // frag bank (4g+t)%32 conflict-free

    const int tid = threadIdx.x, warp = tid >> 5, lane = tid & 31;
    const int g = lane >> 2, t = lane & 3;
    const int bh = blockIdx.y;
    const int b  = bh >> 4;
    const int h  = bh & 15;
    const int q0 = blockIdx.x * 64;

    // --- load Q fragments for this warp's 16 rows directly from global ---
    const int qrow = b * SEQ + q0 + warp * 16;
    uint32_t qa[8][4];
    #pragma unroll
    for (int kt = 0; kt < 8; kt++) {
        qa[kt][0] = f2tf(g_Q[(qrow + g    ) * DMODEL + h * HD + kt * 8 + t    ]);
        qa[kt][1] = f2tf(g_Q[(qrow + g + 8) * DMODEL + h * HD + kt * 8 + t    ]);
        qa[kt][2] = f2tf(g_Q[(qrow + g    ) * DMODEL + h * HD + kt * 8 + t + 4]);
        qa[kt][3] = f2tf(g_Q[(qrow + g + 8) * DMODEL + h * HD + kt * 8 + t + 4]);
    }

    float m2[2]  = {-INFINITY, -INFINITY};   // running max (log2 domain)
    float ls[2]  = {0.f, 0.f};               // per-lane partial row sums
    float o[8][4] = {};

    const int kvbase = b * SEQ;
    const float SC = 0.125f * 1.44269504088896f;  // 1/sqrt(64) * log2(e)

    for (int kv0 = 0; kv0 < SEQ; kv0 += 32) {
        // --- load K,V tiles (32 keys x 64 dims), convert to tf32 ---
        #pragma unroll
        for (int r = 0; r < 4; r++) {
            int i = tid + 128 * r;       // 0..511
            int row = i >> 4;
            int c4  = (i & 15) << 2;
            int gidx = (kvbase + kv0 + row) * DMODEL + h * HD + c4;
            float4 kv = *(const float4*)&g_K[gidx];
            Ks[row][c4 + 0] = __uint_as_float(f2tf(kv.x));
            Ks[row][c4 + 1] = __uint_as_float(f2tf(kv.y));
            Ks[row][c4 + 2] = __uint_as_float(f2tf(kv.z));
            Ks[row][c4 + 3] = __uint_as_float(f2tf(kv.w));
            float4 vv = *(const float4*)&g_V[gidx];
            Vs[row][c4 + 0] = __uint_as_float(f2tf(vv.x));
            Vs[row][c4 + 1] = __uint_as_float(f2tf(vv.y));
            Vs[row][c4 + 2] = __uint_as_float(f2tf(vv.z));
            Vs[row][c4 + 3] = __uint_as_float(f2tf(vv.w));
        }
        __syncthreads();

        // --- S = Q @ K^T ---
        float s[4][4] = {};
        #pragma unroll
        for (int nt = 0; nt < 4; nt++) {
            #pragma unroll
            for (int kt = 0; kt < 8; kt++) {
                uint32_t b0 = __float_as_uint(Ks[nt * 8 + g][kt * 8 + t    ]);
                uint32_t b1 = __float_as_uint(Ks[nt * 8 + g][kt * 8 + t + 4]);
                mma8(s[nt], qa[kt], b0, b1);
            }
        }

        // --- scale into log2 domain, row max (over this tile) ---
        float mx0 = -INFINITY, mx1 = -INFINITY;
        #pragma unroll
        for (int nt = 0; nt < 4; nt++) {
            s[nt][0] *= SC; s[nt][1] *= SC; s[nt][2] *= SC; s[nt][3] *= SC;
            mx0 = fmaxf(mx0, fmaxf(s[nt][0], s[nt][1]));
            mx1 = fmaxf(mx1, fmaxf(s[nt][2], s[nt][3]));
        }
        mx0 = fmaxf(mx0, __shfl_xor_sync(0xffffffffu, mx0, 1));
        mx0 = fmaxf(mx0, __shfl_xor_sync(0xffffffffu, mx0, 2));
        mx1 = fmaxf(mx1, __shfl_xor_sync(0xffffffffu, mx1, 1));
        mx1 = fmaxf(mx1, __shfl_xor_sync(0xffffffffu, mx1, 2));

        float mn0 = fmaxf(m2[0], mx0);
        float mn1 = fmaxf(m2[1], mx1);
        float c0 = exp2f(m2[0] - mn0);
        float c1 = exp2f(m2[1] - mn1);
        m2[0] = mn0; m2[1] = mn1;
        ls[0] *= c0; ls[1] *= c1;
        #pragma unroll
        for (int nt = 0; nt < 8; nt++) {
            o[nt][0] *= c0; o[nt][1] *= c0;
            o[nt][2] *= c1; o[nt][3] *= c1;
        }

        // --- P = exp2(s - m), stash to smem as tf32 for re-fragmenting ---
        #pragma unroll
        for (int nt = 0; nt < 4; nt++) {
            float p0 = exp2f(s[nt][0] - mn0);
            float p1 = exp2f(s[nt][1] - mn0);
            float p2 = exp2f(s[nt][2] - mn1);
            float p3 = exp2f(s[nt][3] - mn1);
            ls[0] += p0 + p1;
            ls[1] += p2 + p3;
            Ps[warp * 16 + g    ][nt * 8 + 2 * t    ] = __uint_as_float(f2tf(p0));
            Ps[warp * 16 + g    ][nt * 8 + 2 * t + 1] = __uint_as_float(f2tf(p1));
            Ps[warp * 16 + g + 8][nt * 8 + 2 * t    ] = __uint_as_float(f2tf(p2));
            Ps[warp * 16 + g + 8][nt * 8 + 2 * t + 1] = __uint_as_float(f2tf(p3));
        }
        __syncwarp();

        // --- O += P @ V ---
        uint32_t pa[4][4];
        #pragma unroll
        for (int kt = 0; kt < 4; kt++) {
            pa[kt][0] = __float_as_uint(Ps[warp * 16 + g    ][kt * 8 + t    ]);
            pa[kt][1] = __float_as_uint(Ps[warp * 16 + g + 8][kt * 8 + t    ]);
            pa[kt][2] = __float_as_uint(Ps[warp * 16 + g    ][kt * 8 + t + 4]);
            pa[kt][3] = __float_as_uint(Ps[warp * 16 + g + 8][kt * 8 + t + 4]);
        }
        #pragma unroll
        for (int nt = 0; nt < 8; nt++) {
            #pragma unroll
            for (int kt = 0; kt < 4; kt++) {
                uint32_t b0 = __float_as_uint(Vs[kt * 8 + t    ][nt * 8 + g]);
                uint32_t b1 = __float_as_uint(Vs[kt * 8 + t + 4][nt * 8 + g]);
                mma8(o[nt], pa[kt], b0, b1);
            }
        }
        __syncthreads();
    }

    // --- normalize and write out[b, s, h*64 + d] ---
    ls[0] += __shfl_xor_sync(0xffffffffu, ls[0], 1);
    ls[0] += __shfl_xor_sync(0xffffffffu, ls[0], 2);
    ls[1] += __shfl_xor_sync(0xffffffffu, ls[1], 1);
    ls[1] += __shfl_xor_sync(0xffffffffu, ls[1], 2);
    float i0 = 1.f / ls[0];
    float i1 = 1.f / ls[1];

    const int orow = b * SEQ + q0 + warp * 16;
    #pragma unroll
    for (int nt = 0; nt < 8; nt++) {
        int col = h * HD + nt * 8 + 2 * t;
        float2 v0 = make_float2(o[nt][0] * i0, o[nt][1] * i0);
        float2 v1 = make_float2(o[nt][2] * i1, o[nt][3] * i1);
        *(float2*)&out[(size_t)(orow + g    ) * DMODEL + col] = v0;
        *(float2*)&out[(size_t)(orow + g + 8) * DMODEL + col] = v1;
    }
}

// ======================================================================
// launch
// ======================================================================
extern "C" void kernel_launch(void* const* d_in, const int* in_sizes, int n_in,
                              void* d_out, int out_size)
{
    const float* x  = (const float*)d_in[0];
    const float* Wq = (const float*)d_in[1];
    const float* bq = (const float*)d_in[2];
    const float* Wk = (const float*)d_in[3];
    const float* bk = (const float*)d_in[4];
    const float* Wv = (const float*)d_in[5];
    const float* bv = (const float*)d_in[6];
    float* out = (float*)d_out;

    dim3 gg(DMODEL / 128, MTOT / 128);      // (8, 32) — 256 blocks, one wave
    qkv_gemm<<<gg, 256>>>(x, Wq, Wk, Wv, bq, bk, bv);

    dim3 ga(SEQ / 64, 2 * NH);              // (32, 32)
    attn_kernel<<<ga, 128>>>(out);
}

// round 12
// speedup vs baseline: 1.6492x; 1.0958x over previous
#include <cuda_runtime.h>
#include <cuda_fp16.h>
#include <cstdint>
#include <math.h>

// Problem constants: B=2, S=2048, D=1024, H=16, hd=64
#define SEQ   2048
#define DMODEL 1024
#define NH    16
#define HD    64
#define MTOT  4096   // B*S

// ---------------- scratch (no cudaMalloc allowed) ----------------
__device__ float g_Q[MTOT * DMODEL];
__device__ float g_K[MTOT * DMODEL];
__device__ float g_V[MTOT * DMODEL];

// ---------------- helpers ----------------
__device__ __forceinline__ uint32_t f2tf(float x) {
    uint32_t u;
    asm("cvt.rna.tf32.f32 %0, %1;" : "=r"(u) : "f"(x));
    return u;
}

__device__ __forceinline__ uint32_t f2h2(float lo, float hi) {
    __half2 h = __floats2half2_rn(lo, hi);   // .x = lo (low 16 bits), .y = hi
    return *(uint32_t*)&h;
}

// tf32 m16n8k8 (attention — unchanged)
__device__ __forceinline__ void mma8(float* c, const uint32_t* a, uint32_t b0, uint32_t b1) {
    asm volatile(
        "mma.sync.aligned.m16n8k8.row.col.f32.tf32.tf32.f32 "
        "{%0,%1,%2,%3}, {%4,%5,%6,%7}, {%8,%9}, {%0,%1,%2,%3};"
        : "+f"(c[0]), "+f"(c[1]), "+f"(c[2]), "+f"(c[3])
        : "r"(a[0]), "r"(a[1]), "r"(a[2]), "r"(a[3]), "r"(b0), "r"(b1));
}

// fp16 m16n8k16 (GEMM — 2x FLOP per instruction vs tf32 m16n8k8)
__device__ __forceinline__ void mma16(float* c, const uint32_t* a, uint32_t b0, uint32_t b1) {
    asm volatile(
        "mma.sync.aligned.m16n8k16.row.col.f32.f16.f16.f32 "
        "{%0,%1,%2,%3}, {%4,%5,%6,%7}, {%8,%9}, {%0,%1,%2,%3};"
        : "+f"(c[0]), "+f"(c[1]), "+f"(c[2]), "+f"(c[3])
        : "r"(a[0]), "r"(a[1]), "r"(a[2]), "r"(a[3]), "r"(b0), "r"(b1));
}

// ======================================================================
// Kernel 1: QKV projection GEMM — fp16 math path (fp16 significand ==
// tf32 significand, so precision is unchanged; fp32 accumulate in HW).
// Same tiling/warp layout/epilogue as the verified R11 kernel:
//  grid (8,32), 1 wave at 2 blocks/SM; phase loop (Wq,Wk,Wv) in-block;
//  raw fp32 + bias epilogue (attention does its own tf32 convert).
// SMEM:
//  Au[row][k/2]  half2(x[row][2k], x[row][2k+1])     stride 20 words
//  Bu[kp][n]     half2(W[2kp][n],  W[2kp+1][n])      stride 132 words
// Both strides chosen conflict-free for the m16n8k16 fragment patterns.
// ======================================================================
__global__ __launch_bounds__(256, 2) void qkv_gemm(
    const float* __restrict__ x,
    const float* __restrict__ Wq, const float* __restrict__ Wk, const float* __restrict__ Wv,
    const float* __restrict__ bq, const float* __restrict__ bk, const float* __restrict__ bv)
{
    __shared__ uint32_t Au[128][20];    // 128 rows x 16 half2 (+4 pad)
    __shared__ uint32_t Bu[16][132];    // 16 k-pairs x 128 half2 (+4 pad)

    const int tid  = threadIdx.x;
    const int warp = tid >> 5, lane = tid & 31;
    const int g = lane >> 2, t = lane & 3;
    const int wr = warp >> 1;          // 0..3 (m)
    const int wc = warp & 1;           // 0..1 (n)
    const int m0 = blockIdx.y * 128;
    const int n0 = blockIdx.x * 128;

    #pragma unroll 1
    for (int phase = 0; phase < 3; phase++) {
        const float* W    = (phase == 0) ? Wq : (phase == 1) ? Wk : Wv;
        const float* bias = (phase == 0) ? bq : (phase == 1) ? bk : bv;
        float* outp       = (phase == 0) ? g_Q : (phase == 1) ? g_K : g_V;

        float acc[2][8][4] = {};

        for (int k0 = 0; k0 < DMODEL; k0 += 32) {
            // --- A fill: 128x32 fp32 -> half2, STS.64 ---
            #pragma unroll
            for (int r = 0; r < 4; r++) {
                int i = tid + 256 * r;           // 0..1023
                int row = i >> 3;
                int c4  = (i & 7) << 2;          // 0,4,...,28
                float4 v = *(const float4*)&x[(m0 + row) * DMODEL + k0 + c4];
                uint2 h;
                h.x = f2h2(v.x, v.y);
                h.y = f2h2(v.z, v.w);
                *(uint2*)&Au[row][c4 >> 1] = h;
            }
            // --- B fill: pack half2(W[2kp][n], W[2kp+1][n]), STS.128 ---
            #pragma unroll
            for (int r = 0; r < 2; r++) {
                int j  = tid + 256 * r;          // 0..511
                int kp = j >> 5;                 // 0..15
                int n  = (j & 31) << 2;          // 0,4,...,124
                const float* w0 = &W[(size_t)(k0 + 2 * kp) * DMODEL + n0 + n];
                const float* w1 = w0 + DMODEL;
                float4 a = *(const float4*)w0;
                float4 b = *(const float4*)w1;
                uint4 h;
                h.x = f2h2(a.x, b.x);
                h.y = f2h2(a.y, b.y);
                h.z = f2h2(a.z, b.z);
                h.w = f2h2(a.w, b.w);
                *(uint4*)&Bu[kp][n] = h;
            }
            __syncthreads();

            // --- two K=16 chunks per 32-k tile ---
            #pragma unroll
            for (int c = 0; c < 2; c++) {
                uint32_t a[2][4], bb[8][2];
                #pragma unroll
                for (int mt = 0; mt < 2; mt++) {
                    int rb = wr * 32 + mt * 16;
                    a[mt][0] = Au[rb + g    ][8 * c + t    ];
                    a[mt][1] = Au[rb + g + 8][8 * c + t    ];
                    a[mt][2] = Au[rb + g    ][8 * c + t + 4];
                    a[mt][3] = Au[rb + g + 8][8 * c + t + 4];
                }
                #pragma unroll
                for (int nt = 0; nt < 8; nt++) {
                    int cb = wc * 64 + nt * 8;
                    bb[nt][0] = Bu[8 * c + t    ][cb + g];
                    bb[nt][1] = Bu[8 * c + t + 4][cb + g];
                }
                #pragma unroll
                for (int mt = 0; mt < 2; mt++)
                    #pragma unroll
                    for (int nt = 0; nt < 8; nt++)
                        mma16(acc[mt][nt], a[mt], bb[nt][0], bb[nt][1]);
            }
            __syncthreads();
        }

        // epilogue: + bias, write row-major (raw fp32, unchanged)
        #pragma unroll
        for (int mt = 0; mt < 2; mt++) {
            int row = m0 + wr * 32 + mt * 16 + g;
            #pragma unroll
            for (int nt = 0; nt < 8; nt++) {
                int col = n0 + wc * 64 + nt * 8 + 2 * t;
                float b0v = bias[col], b1v = bias[col + 1];
                float2 v0 = make_float2(acc[mt][nt][0] + b0v, acc[mt][nt][1] + b1v);
                float2 v1 = make_float2(acc[mt][nt][2] + b0v, acc[mt][nt][3] + b1v);
                *(float2*)&outp[(size_t)row       * DMODEL + col] = v0;
                *(float2*)&outp[(size_t)(row + 8) * DMODEL + col] = v1;
            }
        }
    }
}

// ======================================================================
// Kernel 2: flash attention — EXACT R1/R11 content (verified 294us).
// grid = (SEQ/64, B*NH), 128 threads (4 warps), each warp owns
// 16 q-rows x all keys. KV tiles of 32 keys.
// ======================================================================
__global__ __launch_bounds__(128) void attn_kernel(float* __restrict__ out)
{
    __shared__ float Ks[32][68];   // frag bank (4g+t)%32 conflict-free
    __shared__ float Vs[32][72];   // frag bank (8t+g)%32 conflict-free
    __shared__ float Ps[64][36];   // frag bank (4g+t)%32 conflict-free

    const int tid = threadIdx.x, warp = tid >> 5, lane = tid & 31;
    const int g = lane >> 2, t = lane & 3;
    const int bh = blockIdx.y;
    const int b  = bh >> 4;
    const int h  = bh & 15;
    const int q0 = blockIdx.x * 64;

    // --- load Q fragments for this warp's 16 rows directly from global ---
    const int qrow = b * SEQ + q0 + warp * 16;
    uint32_t qa[8][4];
    #pragma unroll
    for (int kt = 0; kt < 8; kt++) {
        qa[kt][0] = f2tf(g_Q[(qrow + g    ) * DMODEL + h * HD + kt * 8 + t    ]);
        qa[kt][1] = f2tf(g_Q[(qrow + g + 8) * DMODEL + h * HD + kt * 8 + t    ]);
        qa[kt][2] = f2tf(g_Q[(qrow + g    ) * DMODEL + h * HD + kt * 8 + t + 4]);
        qa[kt][3] = f2tf(g_Q[(qrow + g + 8) * DMODEL + h * HD + kt * 8 + t + 4]);
    }

    float m2[2]  = {-INFINITY, -INFINITY};   // running max (log2 domain)
    float ls[2]  = {0.f, 0.f};               // per-lane partial row sums
    float o[8][4] = {};

    const int kvbase = b * SEQ;
    const float SC = 0.125f * 1.44269504088896f;  // 1/sqrt(64) * log2(e)

    for (int kv0 = 0; kv0 < SEQ; kv0 += 32) {
        // --- load K,V tiles (32 keys x 64 dims), convert to tf32 ---
        #pragma unroll
        for (int r = 0; r < 4; r++) {
            int i = tid + 128 * r;       // 0..511
            int row = i >> 4;
            int c4  = (i & 15) << 2;
            int gidx = (kvbase + kv0 + row) * DMODEL + h * HD + c4;
            float4 kv = *(const float4*)&g_K[gidx];
            Ks[row][c4 + 0] = __uint_as_float(f2tf(kv.x));
            Ks[row][c4 + 1] = __uint_as_float(f2tf(kv.y));
            Ks[row][c4 + 2] = __uint_as_float(f2tf(kv.z));
            Ks[row][c4 + 3] = __uint_as_float(f2tf(kv.w));
            float4 vv = *(const float4*)&g_V[gidx];
            Vs[row][c4 + 0] = __uint_as_float(f2tf(vv.x));
            Vs[row][c4 + 1] = __uint_as_float(f2tf(vv.y));
            Vs[row][c4 + 2] = __uint_as_float(f2tf(vv.z));
            Vs[row][c4 + 3] = __uint_as_float(f2tf(vv.w));
        }
        __syncthreads();

        // --- S = Q @ K^T ---
        float s[4][4] = {};
        #pragma unroll
        for (int nt = 0; nt < 4; nt++) {
            #pragma unroll
            for (int kt = 0; kt < 8; kt++) {
                uint32_t b0 = __float_as_uint(Ks[nt * 8 + g][kt * 8 + t    ]);
                uint32_t b1 = __float_as_uint(Ks[nt * 8 + g][kt * 8 + t + 4]);
                mma8(s[nt], qa[kt], b0, b1);
            }
        }

        // --- scale into log2 domain, row max (over this tile) ---
        float mx0 = -INFINITY, mx1 = -INFINITY;
        #pragma unroll
        for (int nt = 0; nt < 4; nt++) {
            s[nt][0] *= SC; s[nt][1] *= SC; s[nt][2] *= SC; s[nt][3] *= SC;
            mx0 = fmaxf(mx0, fmaxf(s[nt][0], s[nt][1]));
            mx1 = fmaxf(mx1, fmaxf(s[nt][2], s[nt][3]));
        }
        mx0 = fmaxf(mx0, __shfl_xor_sync(0xffffffffu, mx0, 1));
        mx0 = fmaxf(mx0, __shfl_xor_sync(0xffffffffu, mx0, 2));
        mx1 = fmaxf(mx1, __shfl_xor_sync(0xffffffffu, mx1, 1));
        mx1 = fmaxf(mx1, __shfl_xor_sync(0xffffffffu, mx1, 2));

        float mn0 = fmaxf(m2[0], mx0);
        float mn1 = fmaxf(m2[1], mx1);
        float c0 = exp2f(m2[0] - mn0);
        float c1 = exp2f(m2[1] - mn1);
        m2[0] = mn0; m2[1] = mn1;
        ls[0] *= c0; ls[1] *= c1;
        #pragma unroll
        for (int nt = 0; nt < 8; nt++) {
            o[nt][0] *= c0; o[nt][1] *= c0;
            o[nt][2] *= c1; o[nt][3] *= c1;
        }

        // --- P = exp2(s - m), stash to smem as tf32 for re-fragmenting ---
        #pragma unroll
        for (int nt = 0; nt < 4; nt++) {
            float p0 = exp2f(s[nt][0] - mn0);
            float p1 = exp2f(s[nt][1] - mn0);
            float p2 = exp2f(s[nt][2] - mn1);
            float p3 = exp2f(s[nt][3] - mn1);
            ls[0] += p0 + p1;
            ls[1] += p2 + p3;
            Ps[warp * 16 + g    ][nt * 8 + 2 * t    ] = __uint_as_float(f2tf(p0));
            Ps[warp * 16 + g    ][nt * 8 + 2 * t + 1] = __uint_as_float(f2tf(p1));
            Ps[warp * 16 + g + 8][nt * 8 + 2 * t    ] = __uint_as_float(f2tf(p2));
            Ps[warp * 16 + g + 8][nt * 8 + 2 * t + 1] = __uint_as_float(f2tf(p3));
        }
        __syncwarp();

        // --- O += P @ V ---
        uint32_t pa[4][4];
        #pragma unroll
        for (int kt = 0; kt < 4; kt++) {
            pa[kt][0] = __float_as_uint(Ps[warp * 16 + g    ][kt * 8 + t    ]);
            pa[kt][1] = __float_as_uint(Ps[warp * 16 + g + 8][kt * 8 + t    ]);
            pa[kt][2] = __float_as_uint(Ps[warp * 16 + g    ][kt * 8 + t + 4]);
            pa[kt][3] = __float_as_uint(Ps[warp * 16 + g + 8][kt * 8 + t + 4]);
        }
        #pragma unroll
        for (int nt = 0; nt < 8; nt++) {
            #pragma unroll
            for (int kt = 0; kt < 4; kt++) {
                uint32_t b0 = __float_as_uint(Vs[kt * 8 + t    ][nt * 8 + g]);
                uint32_t b1 = __float_as_uint(Vs[kt * 8 + t + 4][nt * 8 + g]);
                mma8(o[nt], pa[kt], b0, b1);
            }
        }
        __syncthreads();
    }

    // --- normalize and write out[b, s, h*64 + d] ---
    ls[0] += __shfl_xor_sync(0xffffffffu, ls[0], 1);
    ls[0] += __shfl_xor_sync(0xffffffffu, ls[0], 2);
    ls[1] += __shfl_xor_sync(0xffffffffu, ls[1], 1);
    ls[1] += __shfl_xor_sync(0xffffffffu, ls[1], 2);
    float i0 = 1.f / ls[0];
    float i1 = 1.f / ls[1];

    const int orow = b * SEQ + q0 + warp * 16;
    #pragma unroll
    for (int nt = 0; nt < 8; nt++) {
        int col = h * HD + nt * 8 + 2 * t;
        float2 v0 = make_float2(o[nt][0] * i0, o[nt][1] * i0);
        float2 v1 = make_float2(o[nt][2] * i1, o[nt][3] * i1);
        *(float2*)&out[(size_t)(orow + g    ) * DMODEL + col] = v0;
        *(float2*)&out[(size_t)(orow + g + 8) * DMODEL + col] = v1;
    }
}

// ======================================================================
// launch
// ======================================================================
extern "C" void kernel_launch(void* const* d_in, const int* in_sizes, int n_in,
                              void* d_out, int out_size)
{
    const float* x  = (const float*)d_in[0];
    const float* Wq = (const float*)d_in[1];
    const float* bq = (const float*)d_in[2];
    const float* Wk = (const float*)d_in[3];
    const float* bk = (const float*)d_in[4];
    const float* Wv = (const float*)d_in[5];
    const float* bv = (const float*)d_in[6];
    float* out = (float*)d_out;

    dim3 gg(DMODEL / 128, MTOT / 128);      // (8, 32) — 256 blocks, one wave
    qkv_gemm<<<gg, 256>>>(x, Wq, Wk, Wv, bq, bk, bv);

    dim3 ga(SEQ / 64, 2 * NH);              // (32, 32)
    attn_kernel<<<ga, 128>>>(out);
}

// round 17
// speedup vs baseline: 1.8487x; 1.1210x over previous
#include <cuda_runtime.h>
#include <cuda_fp16.h>
#include <cstdint>
#include <math.h>

// Problem constants: B=2, S=2048, D=1024, H=16, hd=64
#define SEQ   2048
#define DMODEL 1024
#define NH    16
#define HD    64
#define MTOT  4096   // B*S

// ---------------- scratch (no cudaMalloc allowed) ----------------
__device__ float g_Q[MTOT * DMODEL];
__device__ float g_K[MTOT * DMODEL];
__device__ float g_V[MTOT * DMODEL];

// ---------------- helpers ----------------
__device__ __forceinline__ uint32_t f2h2(float lo, float hi) {
    __half2 h = __floats2half2_rn(lo, hi);   // .x = lo (low 16 bits), .y = hi
    return *(uint32_t*)&h;
}

// fp16 m16n8k16: 2x FLOP per instruction vs tf32 m16n8k8; same 11-bit
// significand as tf32, fp32 accumulate -> precision-neutral.
__device__ __forceinline__ void mma16(float* c, const uint32_t* a, uint32_t b0, uint32_t b1) {
    asm volatile(
        "mma.sync.aligned.m16n8k16.row.col.f32.f16.f16.f32 "
        "{%0,%1,%2,%3}, {%4,%5,%6,%7}, {%8,%9}, {%0,%1,%2,%3};"
        : "+f"(c[0]), "+f"(c[1]), "+f"(c[2]), "+f"(c[3])
        : "r"(a[0]), "r"(a[1]), "r"(a[2]), "r"(a[3]), "r"(b0), "r"(b1));
}

// ======================================================================
// Kernel 1: QKV projection GEMM — byte-identical to the R12 winner.
// fp16 math path, grid (8,32) one wave, phase loop in-block,
// raw fp32 + bias epilogue.
// ======================================================================
__global__ __launch_bounds__(256, 2) void qkv_gemm(
    const float* __restrict__ x,
    const float* __restrict__ Wq, const float* __restrict__ Wk, const float* __restrict__ Wv,
    const float* __restrict__ bq, const float* __restrict__ bk, const float* __restrict__ bv)
{
    __shared__ uint32_t Au[128][20];    // 128 rows x 16 half2 (+4 pad)
    __shared__ uint32_t Bu[16][132];    // 16 k-pairs x 128 half2 (+4 pad)

    const int tid  = threadIdx.x;
    const int warp = tid >> 5, lane = tid & 31;
    const int g = lane >> 2, t = lane & 3;
    const int wr = warp >> 1;          // 0..3 (m)
    const int wc = warp & 1;           // 0..1 (n)
    const int m0 = blockIdx.y * 128;
    const int n0 = blockIdx.x * 128;

    #pragma unroll 1
    for (int phase = 0; phase < 3; phase++) {
        const float* W    = (phase == 0) ? Wq : (phase == 1) ? Wk : Wv;
        const float* bias = (phase == 0) ? bq : (phase == 1) ? bk : bv;
        float* outp       = (phase == 0) ? g_Q : (phase == 1) ? g_K : g_V;

        float acc[2][8][4] = {};

        for (int k0 = 0; k0 < DMODEL; k0 += 32) {
            // --- A fill: 128x32 fp32 -> half2, STS.64 ---
            #pragma unroll
            for (int r = 0; r < 4; r++) {
                int i = tid + 256 * r;           // 0..1023
                int row = i >> 3;
                int c4  = (i & 7) << 2;          // 0,4,...,28
                float4 v = *(const float4*)&x[(m0 + row) * DMODEL + k0 + c4];
                uint2 h;
                h.x = f2h2(v.x, v.y);
                h.y = f2h2(v.z, v.w);
                *(uint2*)&Au[row][c4 >> 1] = h;
            }
            // --- B fill: pack half2(W[2kp][n], W[2kp+1][n]), STS.128 ---
            #pragma unroll
            for (int r = 0; r < 2; r++) {
                int j  = tid + 256 * r;          // 0..511
                int kp = j >> 5;                 // 0..15
                int n  = (j & 31) << 2;          // 0,4,...,124
                const float* w0 = &W[(size_t)(k0 + 2 * kp) * DMODEL + n0 + n];
                const float* w1 = w0 + DMODEL;
                float4 a = *(const float4*)w0;
                float4 b = *(const float4*)w1;
                uint4 h;
                h.x = f2h2(a.x, b.x);
                h.y = f2h2(a.y, b.y);
                h.z = f2h2(a.z, b.z);
                h.w = f2h2(a.w, b.w);
                *(uint4*)&Bu[kp][n] = h;
            }
            __syncthreads();

            // --- two K=16 chunks per 32-k tile ---
            #pragma unroll
            for (int c = 0; c < 2; c++) {
                uint32_t a[2][4], bb[8][2];
                #pragma unroll
                for (int mt = 0; mt < 2; mt++) {
                    int rb = wr * 32 + mt * 16;
                    a[mt][0] = Au[rb + g    ][8 * c + t    ];
                    a[mt][1] = Au[rb + g + 8][8 * c + t    ];
                    a[mt][2] = Au[rb + g    ][8 * c + t + 4];
                    a[mt][3] = Au[rb + g + 8][8 * c + t + 4];
                }
                #pragma unroll
                for (int nt = 0; nt < 8; nt++) {
                    int cb = wc * 64 + nt * 8;
                    bb[nt][0] = Bu[8 * c + t    ][cb + g];
                    bb[nt][1] = Bu[8 * c + t + 4][cb + g];
                }
                #pragma unroll
                for (int mt = 0; mt < 2; mt++)
                    #pragma unroll
                    for (int nt = 0; nt < 8; nt++)
                        mma16(acc[mt][nt], a[mt], bb[nt][0], bb[nt][1]);
            }
            __syncthreads();
        }

        // epilogue: + bias, write row-major (raw fp32, unchanged)
        #pragma unroll
        for (int mt = 0; mt < 2; mt++) {
            int row = m0 + wr * 32 + mt * 16 + g;
            #pragma unroll
            for (int nt = 0; nt < 8; nt++) {
                int col = n0 + wc * 64 + nt * 8 + 2 * t;
                float b0v = bias[col], b1v = bias[col + 1];
                float2 v0 = make_float2(acc[mt][nt][0] + b0v, acc[mt][nt][1] + b1v);
                float2 v1 = make_float2(acc[mt][nt][2] + b0v, acc[mt][nt][3] + b1v);
                *(float2*)&outp[(size_t)row       * DMODEL + col] = v0;
                *(float2*)&outp[(size_t)(row + 8) * DMODEL + col] = v1;
            }
        }
    }
}

// ======================================================================
// Kernel 2: flash attention — R1 structure, fp16 m16n8k16 math.
// grid = (SEQ/64, B*NH), 128 threads (4 warps), warp owns 16 q-rows.
// Same warp mapping, same C-fragment positions (softmax & epilogue code
// unchanged from the verified R1 kernel); MMA count, b-frag LDS, P
// round-trip, fill STS and cvt all HALVED via half2 packing.
// SMEM layouts (uint32 words, all frag accesses bank-conflict-free):
//  Khs[key][d/2]   half2(K[key][2d'],K[key][2d'+1])  stride 36 (banks 4g+t)
//  Vp [kp][d]      half2(V[2kp][d], V[2kp+1][d])     stride 72 (banks 8t+g)
//  Pp [row][c/2]   half2(P[row][2c'],P[row][2c'+1])  stride 20 (banks 20g+t)
// ======================================================================
__global__ __launch_bounds__(128, 4) void attn_kernel(float* __restrict__ out)
{
    __shared__ uint32_t Khs[32][36];
    __shared__ uint32_t Vp [16][72];
    __shared__ uint32_t Pp [64][20];

    const int tid = threadIdx.x, warp = tid >> 5, lane = tid & 31;
    const int g = lane >> 2, t = lane & 3;
    const int bh = blockIdx.y;
    const int b  = bh >> 4;
    const int h  = bh & 15;
    const int q0 = blockIdx.x * 64;

    // --- Q fragments: 4 chunks of K=16, packed half2 from fp32 g_Q ---
    const int qrow = b * SEQ + q0 + warp * 16;
    uint32_t qa[4][4];
    {
        const size_t r0 = (size_t)(qrow + g    ) * DMODEL + h * HD;
        const size_t r8 = (size_t)(qrow + g + 8) * DMODEL + h * HD;
        #pragma unroll
        for (int c = 0; c < 4; c++) {
            float2 u0 = *(const float2*)&g_Q[r0 + c * 16 + 2 * t    ];
            float2 u1 = *(const float2*)&g_Q[r8 + c * 16 + 2 * t    ];
            float2 u2 = *(const float2*)&g_Q[r0 + c * 16 + 2 * t + 8];
            float2 u3 = *(const float2*)&g_Q[r8 + c * 16 + 2 * t + 8];
            qa[c][0] = f2h2(u0.x, u0.y);
            qa[c][1] = f2h2(u1.x, u1.y);
            qa[c][2] = f2h2(u2.x, u2.y);
            qa[c][3] = f2h2(u3.x, u3.y);
        }
    }

    float m2[2]  = {-INFINITY, -INFINITY};   // running max (log2 domain)
    float ls[2]  = {0.f, 0.f};               // per-lane partial row sums
    float o[8][4] = {};

    const int kvbase = b * SEQ;
    const float SC = 0.125f * 1.44269504088896f;  // 1/sqrt(64) * log2(e)

    // fill roles
    const int krow = tid >> 2;               // 0..31 (K fill: key row)
    const int kch  = (tid & 3) * 16;         // dim base 0,16,32,48
    const int vkp  = tid >> 3;               // 0..15 (V fill: key pair)
    const int vdc  = (tid & 7) * 8;          // dim base 0..56

    const int rg = warp * 16 + g;

    for (int kv0 = 0; kv0 < SEQ; kv0 += 32) {
        // --- K fill: pack adjacent dims per key ---
        {
            const float* kp = &g_K[(size_t)(kvbase + kv0 + krow) * DMODEL + h * HD + kch];
            float4 a0 = *(const float4*)(kp     );
            float4 a1 = *(const float4*)(kp + 4 );
            float4 a2 = *(const float4*)(kp + 8 );
            float4 a3 = *(const float4*)(kp + 12);
            uint4 h0, h1;
            h0.x = f2h2(a0.x, a0.y); h0.y = f2h2(a0.z, a0.w);
            h0.z = f2h2(a1.x, a1.y); h0.w = f2h2(a1.z, a1.w);
            h1.x = f2h2(a2.x, a2.y); h1.y = f2h2(a2.z, a2.w);
            h1.z = f2h2(a3.x, a3.y); h1.w = f2h2(a3.z, a3.w);
            *(uint4*)&Khs[krow][(kch >> 1)    ] = h0;
            *(uint4*)&Khs[krow][(kch >> 1) + 4] = h1;
        }
        // --- V fill: pack adjacent keys per dim ---
        {
            const float* v0 = &g_V[(size_t)(kvbase + kv0 + 2 * vkp) * DMODEL + h * HD + vdc];
            const float* v1 = v0 + DMODEL;
            float4 x0 = *(const float4*)(v0    );
            float4 x1 = *(const float4*)(v0 + 4);
            float4 y0 = *(const float4*)(v1    );
            float4 y1 = *(const float4*)(v1 + 4);
            uint4 h0, h1;
            h0.x = f2h2(x0.x, y0.x); h0.y = f2h2(x0.y, y0.y);
            h0.z = f2h2(x0.z, y0.z); h0.w = f2h2(x0.w, y0.w);
            h1.x = f2h2(x1.x, y1.x); h1.y = f2h2(x1.y, y1.y);
            h1.z = f2h2(x1.z, y1.z); h1.w = f2h2(x1.w, y1.w);
            *(uint4*)&Vp[vkp][vdc    ] = h0;
            *(uint4*)&Vp[vkp][vdc + 4] = h1;
        }
        __syncthreads();

        // --- S = Q @ K^T : 16 mma16 (was 32 mma8) ---
        float s[4][4] = {};
        #pragma unroll
        for (int nt = 0; nt < 4; nt++) {
            #pragma unroll
            for (int c = 0; c < 4; c++) {
                uint32_t b0 = Khs[nt * 8 + g][8 * c + t    ];
                uint32_t b1 = Khs[nt * 8 + g][8 * c + t + 4];
                mma16(s[nt], qa[c], b0, b1);
            }
        }

        // --- scale into log2 domain, row max (identical to R1) ---
        float mx0 = -INFINITY, mx1 = -INFINITY;
        #pragma unroll
        for (int nt = 0; nt < 4; nt++) {
            s[nt][0] *= SC; s[nt][1] *= SC; s[nt][2] *= SC; s[nt][3] *= SC;
            mx0 = fmaxf(mx0, fmaxf(s[nt][0], s[nt][1]));
            mx1 = fmaxf(mx1, fmaxf(s[nt][2], s[nt][3]));
        }
        mx0 = fmaxf(mx0, __shfl_xor_sync(0xffffffffu, mx0, 1));
        mx0 = fmaxf(mx0, __shfl_xor_sync(0xffffffffu, mx0, 2));
        mx1 = fmaxf(mx1, __shfl_xor_sync(0xffffffffu, mx1, 1));
        mx1 = fmaxf(mx1, __shfl_xor_sync(0xffffffffu, mx1, 2));

        float mn0 = fmaxf(m2[0], mx0);
        float mn1 = fmaxf(m2[1], mx1);
        float c0 = exp2f(m2[0] - mn0);
        float c1 = exp2f(m2[1] - mn1);
        m2[0] = mn0; m2[1] = mn1;
        ls[0] *= c0; ls[1] *= c1;
        #pragma unroll
        for (int nt = 0; nt < 8; nt++) {
            o[nt][0] *= c0; o[nt][1] *= c0;
            o[nt][2] *= c1; o[nt][3] *= c1;
        }

        // --- P = exp2(s - m); p0,p1 are adjacent cols -> pack half2 ---
        #pragma unroll
        for (int nt = 0; nt < 4; nt++) {
            float p0 = exp2f(s[nt][0] - mn0);
            float p1 = exp2f(s[nt][1] - mn0);
            float p2 = exp2f(s[nt][2] - mn1);
            float p3 = exp2f(s[nt][3] - mn1);
            ls[0] += p0 + p1;
            ls[1] += p2 + p3;
            Pp[rg    ][nt * 4 + t] = f2h2(p0, p1);
            Pp[rg + 8][nt * 4 + t] = f2h2(p2, p3);
        }
        __syncwarp();

        // --- reload P as A-frags: 8 LDS.32 (was 16) ---
        uint32_t pa[2][4];
        #pragma unroll
        for (int c2 = 0; c2 < 2; c2++) {
            pa[c2][0] = Pp[rg    ][8 * c2 + t    ];
            pa[c2][1] = Pp[rg + 8][8 * c2 + t    ];
            pa[c2][2] = Pp[rg    ][8 * c2 + t + 4];
            pa[c2][3] = Pp[rg + 8][8 * c2 + t + 4];
        }

        // --- O += P @ V : 16 mma16 (was 32 mma8) ---
        #pragma unroll
        for (int nt = 0; nt < 8; nt++) {
            #pragma unroll
            for (int c2 = 0; c2 < 2; c2++) {
                uint32_t b0 = Vp[8 * c2 + t    ][nt * 8 + g];
                uint32_t b1 = Vp[8 * c2 + t + 4][nt * 8 + g];
                mma16(o[nt], pa[c2], b0, b1);
            }
        }
        __syncthreads();
    }

    // --- normalize and write out[b, s, h*64 + d] (identical to R1) ---
    ls[0] += __shfl_xor_sync(0xffffffffu, ls[0], 1);
    ls[0] += __shfl_xor_sync(0xffffffffu, ls[0], 2);
    ls[1] += __shfl_xor_sync(0xffffffffu, ls[1], 1);
    ls[1] += __shfl_xor_sync(0xffffffffu, ls[1], 2);
    float i0 = 1.f / ls[0];
    float i1 = 1.f / ls[1];

    const int orow = b * SEQ + q0 + warp * 16;
    #pragma unroll
    for (int nt = 0; nt < 8; nt++) {
        int col = h * HD + nt * 8 + 2 * t;
        float2 v0 = make_float2(o[nt][0] * i0, o[nt][1] * i0);
        float2 v1 = make_float2(o[nt][2] * i1, o[nt][3] * i1);
        *(float2*)&out[(size_t)(orow + g    ) * DMODEL + col] = v0;
        *(float2*)&out[(size_t)(orow + g + 8) * DMODEL + col] = v1;
    }
}

// ======================================================================
// launch
// ======================================================================
extern "C" void kernel_launch(void* const* d_in, const int* in_sizes, int n_in,
                              void* d_out, int out_size)
{
    const float* x  = (const float*)d_in[0];
    const float* Wq = (const float*)d_in[1];
    const float* bq = (const float*)d_in[2];
    const float* Wk = (const float*)d_in[3];
    const float* bk = (const float*)d_in[4];
    const float* Wv = (const float*)d_in[5];
    const float* bv = (const float*)d_in[6];
    float* out = (float*)d_out;

    dim3 gg(DMODEL / 128, MTOT / 128);      // (8, 32) — 256 blocks, one wave
    qkv_gemm<<<gg, 256>>>(x, Wq, Wk, Wv, bq, bk, bv);

    dim3 ga(SEQ / 64, 2 * NH);              // (32, 32)
    attn_kernel<<<ga, 128>>>(out);
}